// round 7
// baseline (speedup 1.0000x reference)
#include <cuda_runtime.h>
#include <cstdint>
#include <math.h>

// Problem constants
#define NB    8192
#define NT    64
#define NF    64
#define WIN   30
#define BEGIN 15
#define ROW0  34            // BEGIN + CONV - 1
#define OUTROW 320
#define OUTB  (WIN * OUTROW)
#define FULLM 0xffffffffu

// Scratch (device globals: allowed; no allocation)
__device__ float          g_xT[WIN * NF * NB];    // 63 MB: x rows 34..63, [w][e][b]
__device__ unsigned short g_rank[WIN * NF * NB];  // 31.5 MB: ranks, [w][e][b]

// ============================================================================
// Stats kernel (unchanged, known-good): one thread per (b, e).
// ============================================================================
__global__ __launch_bounds__(256) void stats_kernel(const float* __restrict__ x,
                                                    float* __restrict__ out) {
    int tid = threadIdx.x;
    int e = tid & 63;
    int b = blockIdx.x * 4 + (tid >> 6);

    const float* p = x + (size_t)b * (NT * NF) + BEGIN * NF + e;
    float* ob = out + (size_t)b * OUTB + e;

    float buf[20];
    float S1 = 0.f, S2 = 0.f;
#pragma unroll
    for (int i = 0; i < 20; i++) {
        float t = p[i * NF];
        buf[i] = t;
        S1 += t;
        S2 = fmaf(t, t, S2);
    }
    {
        float mx = buf[0], mn = buf[0];
#pragma unroll
        for (int i = 1; i < 20; i++) { mx = fmaxf(mx, buf[i]); mn = fminf(mn, buf[i]); }
        float mean = S1 * 0.05f;
        float var = fmaf(-S1, mean, S2) * (1.0f / 19.0f);
        float sd = sqrtf(fmaxf(var, 0.f));
        ob[0] = mean; ob[64] = sd; ob[192] = mx; ob[256] = mn;
    }
#pragma unroll
    for (int w = 1; w < WIN; w++) {
        int s = (w - 1) % 20;
        float vo = buf[s];
        float vn = p[(w + 19) * NF];
        S1 += vn - vo;
        S2 = S2 + fmaf(vn, vn, -vo * vo);
        buf[s] = vn;

        float mx = buf[0], mn = buf[0];
#pragma unroll
        for (int i = 1; i < 20; i++) { mx = fmaxf(mx, buf[i]); mn = fminf(mn, buf[i]); }
        float mean = S1 * 0.05f;
        float var = fmaf(-S1, mean, S2) * (1.0f / 19.0f);
        float sd = sqrtf(fmaxf(var, 0.f));
        float* o = ob + w * OUTROW;
        o[0] = mean; o[64] = sd; o[192] = mx; o[256] = mn;
    }
}

// ============================================================================
// Pre-transpose: x[b][ROW0+w][e] -> g_xT[w][e][b]. Both sides coalesced.
// Grid (64 b-tiles of 128, WIN), 256 threads, 33.8 KB static smem.
// ============================================================================
__global__ __launch_bounds__(256) void pretrans_kernel(const float* __restrict__ x) {
    __shared__ float tile[64][132];   // [e][b_local], pad 132 (float4-aligned reads)
    int t = threadIdx.x;
    int w = blockIdx.y;
    int b0 = blockIdx.x * 128;
    const float* src = x + (size_t)(ROW0 + w) * NF;
#pragma unroll
    for (int i = 0; i < 32; i++) {
        int e = t & 63;
        int bl = i * 4 + (t >> 6);
        tile[e][bl] = src[(size_t)(b0 + bl) * (NT * NF) + e];
    }
    __syncthreads();
#pragma unroll
    for (int i = 0; i < 8; i++) {
        int e = i * 8 + (t >> 5);
        int b4 = (t & 31) * 4;
        float4 v = *(const float4*)&tile[e][b4];
        *(float4*)&g_xT[(size_t)(w * 64 + e) * NB + b0 + b4] = v;
    }
}

// ============================================================================
// Rank kernel: one block per (w, e) column. Atomic-free.
//
// meta = (bucket13 << 13) | b. Initial order is b-ascending, so two stable
// LSB radix passes on the bucket (8-bit digit, then 5-bit digit) yield a
// full sort by (bucket, b). Counting uses per-warp counters updated by a
// __match_any_sync-elected leader (no atomics, no races); stability holds
// because elements map to (warp-major, round, lane) = b order, and the scan
// orders counters as s = digit*32 + warp. Counter addr w*257+d (pass A) /
// w*33+d (pass B); scan address (s&31)*stride+(s>>5) is bank-conflict-free.
// Pass B scatters in place from registers. Exact rank = run_start + within-
// run comparisons (earlier idx ties count: dk_q <= dk; later idx: dk_q < dk).
// ============================================================================
#define RANK_SMEM ((8192 + 8192 + 8224 + 256 + 256 + 32) * 4)   // 100,608 B

__global__ __launch_bounds__(1024, 1) void rank_kernel() {
    extern __shared__ uint32_t smu[];
    uint32_t* dkeyArr   = smu;            // 8192: descending-monotone keys by b
    uint32_t* meta      = smu + 8192;     // 8192: radix array (in-place pass B)
    uint32_t* cnt       = smu + 16384;    // 8224: counters / prefix / rankArr
    uint32_t* cellBase  = smu + 24608;    // 256
    uint32_t* cellShift = smu + 24864;    // 256
    uint32_t* warpsum   = smu + 25120;    // 32
    uint16_t* rankArr   = (uint16_t*)cnt; // overlays cnt after pass B

    const int tid = threadIdx.x, lane = tid & 31, warp = tid >> 5;
    const int e = blockIdx.x, w = blockIdx.y;

    // ---- density-adapted bucket tables (exactly monotone in dkey) ----
    uint32_t sz = 0, incT = 0;
    if (tid < 256) {
        int p = (tid >= 128) ? (tid - 128) : (127 - tid);   // = exp>>1 of |v|
        int sh;
        if      (p == 63)            sh = 13;
        else if (p == 62)            sh = 14;
        else if (p == 64 || p == 61) sh = 16;
        else if (p == 60)            sh = 17;
        else if (p == 59)            sh = 18;
        else                         sh = 24;
        cellShift[tid] = (uint32_t)sh;
        sz = 1u << (24 - sh);
        incT = sz;
#pragma unroll
        for (int o = 1; o < 32; o <<= 1) {
            uint32_t tt = __shfl_up_sync(FULLM, incT, o);
            if (lane >= o) incT += tt;
        }
        if (lane == 31) warpsum[warp] = incT;
    }
    __syncthreads();
    if (tid < 256) {
        uint32_t wb = 0;
        for (int i = 0; i < warp; i++) wb += warpsum[i];
        cellBase[tid] = wb + incT - sz;     // exclusive base; total = 7796 < 8192
    }
    for (int i = tid; i < 8224; i += 1024) cnt[i] = 0;
    __syncthreads();

    // ---- load (coalesced from g_xT) + pass A counting (match-based) ----
    const float* xc = g_xT + (size_t)(w * 64 + e) * NB;
    uint32_t offsA[8];
#pragma unroll
    for (int j = 0; j < 8; j++) {
        int b = warp * 256 + j * 32 + lane;         // b order = (warp, round, lane)
        float v = xc[b];
        uint32_t u = __float_as_uint(v);
        uint32_t m = (u & 0x80000000u) ? ~u : (u | 0x80000000u);
        uint32_t dk = ~m;                            // descending-monotone key
        dkeyArr[b] = dk;
        uint32_t j8 = dk >> 24;
        uint32_t bkt = cellBase[j8] + ((dk & 0x00FFFFFFu) >> cellShift[j8]);
        uint32_t d = bkt & 255u;
        uint32_t mk = __match_any_sync(FULLM, d);
        int ldr = __ffs(mk) - 1;
        uint32_t pre = __popc(mk & ((1u << lane) - 1u));
        uint32_t old = 0;
        if (lane == ldr) { uint32_t* cp = &cnt[warp * 257 + d]; old = *cp; *cp = old + __popc(mk); }
        old = __shfl_sync(FULLM, old, ldr);
        offsA[j] = old + pre;
    }
    __syncthreads();

    // ---- scan A: 8192 counters in semantic order s = d*32 + w ----
    {
        uint32_t vv[8], sum = 0;
        int s0 = tid * 8;
#pragma unroll
        for (int k = 0; k < 8; k++) {
            int s = s0 + k;
            vv[k] = cnt[(s & 31) * 257 + (s >> 5)];
            sum += vv[k];
        }
        uint32_t inc = sum;
#pragma unroll
        for (int o = 1; o < 32; o <<= 1) {
            uint32_t tt = __shfl_up_sync(FULLM, inc, o);
            if (lane >= o) inc += tt;
        }
        if (lane == 31) warpsum[warp] = inc;
        __syncthreads();
        if (warp == 0) {
            uint32_t v2 = warpsum[lane], wi = v2;
#pragma unroll
            for (int o = 1; o < 32; o <<= 1) {
                uint32_t tt = __shfl_up_sync(FULLM, wi, o);
                if (lane >= o) wi += tt;
            }
            warpsum[lane] = wi - v2;
        }
        __syncthreads();
        uint32_t run = warpsum[warp] + inc - sum;
#pragma unroll
        for (int k = 0; k < 8; k++) {
            int s = s0 + k;
            uint32_t tv = vv[k];
            cnt[(s & 31) * 257 + (s >> 5)] = run;
            run += tv;
        }
    }
    __syncthreads();

    // ---- scatter A -> meta (sorted by bucket low byte, stable in b) ----
#pragma unroll
    for (int j = 0; j < 8; j++) {
        int b = warp * 256 + j * 32 + lane;
        uint32_t dk = dkeyArr[b];
        uint32_t j8 = dk >> 24;
        uint32_t bkt = cellBase[j8] + ((dk & 0x00FFFFFFu) >> cellShift[j8]);
        uint32_t pos = cnt[warp * 257 + (bkt & 255u)] + offsA[j];
        meta[pos] = (bkt << 13) | (uint32_t)b;
    }
    __syncthreads();

    // ---- pass B: 5-bit digit (bucket >> 8); counters cnt[w*33+d] ----
    cnt[tid] = 0;
    if (tid < 32) cnt[1024 + tid] = 0;
    __syncthreads();
    uint32_t mR[8], offsB[8];
#pragma unroll
    for (int j = 0; j < 8; j++) {
        int p = warp * 256 + j * 32 + lane;          // current (pass-A) order
        uint32_t m = meta[p];
        mR[j] = m;
        uint32_t d = m >> 21;
        uint32_t mk = __match_any_sync(FULLM, d);
        int ldr = __ffs(mk) - 1;
        uint32_t pre = __popc(mk & ((1u << lane) - 1u));
        uint32_t old = 0;
        if (lane == ldr) { uint32_t* cp = &cnt[warp * 33 + d]; old = *cp; *cp = old + __popc(mk); }
        old = __shfl_sync(FULLM, old, ldr);
        offsB[j] = old + pre;
    }
    __syncthreads();
    // scan B: 1024 counters, semantic s = d*32 + w at addr (s&31)*33 + (s>>5)
    {
        uint32_t vb = cnt[(tid & 31) * 33 + (tid >> 5)];
        uint32_t inc = vb;
#pragma unroll
        for (int o = 1; o < 32; o <<= 1) {
            uint32_t tt = __shfl_up_sync(FULLM, inc, o);
            if (lane >= o) inc += tt;
        }
        if (lane == 31) warpsum[warp] = inc;
        __syncthreads();
        if (warp == 0) {
            uint32_t v2 = warpsum[lane], wi = v2;
#pragma unroll
            for (int o = 1; o < 32; o <<= 1) {
                uint32_t tt = __shfl_up_sync(FULLM, wi, o);
                if (lane >= o) wi += tt;
            }
            warpsum[lane] = wi - v2;
        }
        __syncthreads();
        cnt[(tid & 31) * 33 + (tid >> 5)] = warpsum[warp] + inc - vb;
    }
    __syncthreads();
    // scatter B in place (values held in registers; safe after the syncs)
#pragma unroll
    for (int j = 0; j < 8; j++) {
        uint32_t pos = cnt[warp * 33 + (mR[j] >> 21)] + offsB[j];
        meta[pos] = mR[j];
    }
    __syncthreads();

    // ---- resolve exact ranks: runs of equal bucket are b-ascending ----
#pragma unroll 1
    for (int k = 0; k < 8; k++) {
        int p = k * 1024 + tid;                       // lane-consecutive loads
        uint32_t m = meta[p];
        uint32_t bk = m >> 13;
        uint32_t idx = m & 8191u;
        uint32_t dk = dkeyArr[idx];
        int s = p;
        while (s > 0 && (meta[s - 1] >> 13) == bk) s--;
        uint32_t r = (uint32_t)s;                     // earlier buckets: dk strictly smaller
        for (int q = s; q < p; q++)                   // earlier idx: ties count
            r += (dkeyArr[meta[q] & 8191u] <= dk) ? 1u : 0u;
        for (int q = p + 1; q < NB; q++) {            // later idx: ties don't
            uint32_t mq = meta[q];
            if ((mq >> 13) != bk) break;
            r += (dkeyArr[mq & 8191u] < dk) ? 1u : 0u;
        }
        rankArr[idx] = (uint16_t)r;
    }
    __syncthreads();

    // ---- coalesced u16 store to g_rank[w][e][b] ----
    uint4 ov = ((const uint4*)rankArr)[tid];
    ((uint4*)(g_rank + (size_t)(w * 64 + e) * NB))[tid] = ov;
}

// ============================================================================
// Post-transpose: g_rank[w][e][b] u16 -> out[b][w*320+128+e] float, coalesced.
// Grid (64 b-tiles of 128, WIN), 256 threads, 33.3 KB static smem.
// ============================================================================
__global__ __launch_bounds__(256) void posttrans_kernel(float* __restrict__ out) {
    __shared__ float tf[128][65];   // [b_local][e], pad 65
    int t = threadIdx.x;
    int w = blockIdx.y;
    int b0 = blockIdx.x * 128;
    const float inv = 1.0f / 8192.0f;
    const uint32_t* gr32 = (const uint32_t*)g_rank;
#pragma unroll
    for (int i = 0; i < 16; i++) {
        int idx = t + i * 256;
        int e = idx >> 6;          // 0..63
        int c = idx & 63;          // u32 within 128-b tile (2 b's each)
        uint32_t v = gr32[(size_t)(w * 64 + e) * (NB / 2) + (b0 >> 1) + c];
        tf[2 * c][e]     = (float)(v & 0xffffu) * inv;
        tf[2 * c + 1][e] = (float)(v >> 16) * inv;
    }
    __syncthreads();
#pragma unroll
    for (int i = 0; i < 8; i++) {
        int b = i * 16 + (t >> 4);
        int e4 = (t & 15) * 4;
        float4 o;
        o.x = tf[b][e4];     o.y = tf[b][e4 + 1];
        o.z = tf[b][e4 + 2]; o.w = tf[b][e4 + 3];
        *(float4*)&out[(size_t)(b0 + b) * OUTB + w * OUTROW + 128 + e4] = o;
    }
}

// ============================================================================
extern "C" void kernel_launch(void* const* d_in, const int* in_sizes, int n_in,
                              void* d_out, int out_size) {
    const float* x = (const float*)d_in[0];
    float* out = (float*)d_out;
    (void)in_sizes; (void)n_in; (void)out_size;

    cudaFuncSetAttribute(rank_kernel, cudaFuncAttributeMaxDynamicSharedMemorySize,
                         RANK_SMEM);

    pretrans_kernel<<<dim3(64, WIN), 256>>>(x);
    rank_kernel<<<dim3(64, WIN), 1024, RANK_SMEM>>>();
    posttrans_kernel<<<dim3(64, WIN), 256>>>(out);
    stats_kernel<<<NB / 4, 256>>>(x, out);
}